// round 12
// baseline (speedup 1.0000x reference)
#include <cuda_runtime.h>
#include <cuda_bf16.h>
#include <cstdint>

// ============================================================================
// VQ quantizer: for each of N=131072 vectors z (C=256), argmin_k over K=512
// codes of ||z-e_k||^2, output e[argmin] in [B,C,H,W] layout.
//
//   1) prep_e:  e fp32 -> bf16 codebook + fp32 ||e_k||^2
//   2) zero:    reset rescore queue counter
//   3) gemm:    bf16 mma.sync GEMM, 4x2 warp grid (32x32 tile/warp),
//               per-warp running-min + margin candidates, two-half final
//               filter, inline classify, coalesced z export. 2 CTAs/SM.
//   4) rescore: fp64 exact scores for ambiguous rows (coalesced z reads)
//   5) gather:  out[b,c,h,w] = e[best[n]][c], 64-row blocks, float2 stores
// ============================================================================

#define BATCH 128
#define CDIM  256
#define HW    1024
#define NVEC  (BATCH * HW)
#define KCODE 512
#define CAP   16
#define MARGIN  2.0f
#define FMARGIN 1.5f
#define MAXQ  49152

#define BM 128
#define BN 64
#define NCHUNK (KCODE / BN)
#define ZS  264                 // bf16 elements per smem row (256 + 8 pad)
#define ZSB 528                 // bytes per smem row

// smem byte offsets (103 KB -> 2 CTAs/SM)
#define OFF_EN    0                        // 512 f32   -> 2048
#define OFF_CNT   2048                     // 128 i32   -> 2560
#define OFF_RMIN2 2560                     // 128x2 f32 -> 3584
#define OFF_QSLOT 3584                     // 128 i32   -> 4096
#define OFF_Z     4096                     // 128*528   -> 71680
#define OFF_E     71680                    // 64*528    -> 105472
#define SMEM_TOTAL 105472

#define GROWS 64                           // gather rows per block
#define GSTRIDE 257
#define GATHER_SMEM (GROWS * GSTRIDE * 4 + GROWS * 4)

// --------------------------- scratch (device globals) -----------------------
__device__ __nv_bfloat16 g_eb[KCODE * CDIM];
__device__ float         g_enf[KCODE];
__device__ int           g_best[NVEC];
__device__ float         g_csv[(size_t)NVEC * CAP];
__device__ int           g_civ[(size_t)NVEC * CAP];
__device__ int           g_qn[NVEC];
__device__ int           g_qc[NVEC];
__device__ int           g_qcd[(size_t)NVEC * CAP];
__device__ float         g_zq[(size_t)MAXQ * CDIM];
__device__ int           g_qcnt;

// --------------------------- asm helpers -------------------------------------
__device__ __forceinline__ uint32_t sptr(const void* p) {
    return (uint32_t)__cvta_generic_to_shared(p);
}
__device__ __forceinline__ void cp16(uint32_t dst, const void* src) {
    asm volatile("cp.async.cg.shared.global [%0], [%1], 16;" :: "r"(dst), "l"(src));
}
__device__ __forceinline__ void ldsm_x4(uint32_t* d, uint32_t addr) {
    asm volatile("ldmatrix.sync.aligned.m8n8.x4.shared.b16 {%0,%1,%2,%3}, [%4];"
                 : "=r"(d[0]), "=r"(d[1]), "=r"(d[2]), "=r"(d[3]) : "r"(addr));
}
__device__ __forceinline__ void mma16816(float* c, const uint32_t* a, const uint32_t* b) {
    asm volatile(
        "mma.sync.aligned.m16n8k16.row.col.f32.bf16.bf16.f32 "
        "{%0,%1,%2,%3}, {%4,%5,%6,%7}, {%8,%9}, {%0,%1,%2,%3};"
        : "+f"(c[0]), "+f"(c[1]), "+f"(c[2]), "+f"(c[3])
        : "r"(a[0]), "r"(a[1]), "r"(a[2]), "r"(a[3]), "r"(b[0]), "r"(b[1]));
}

// --------------------------- 1) codebook prep --------------------------------
__global__ void k_prep_e(const float* __restrict__ e) {
    int k = blockIdx.x, c = threadIdx.x;
    float v = e[k * CDIM + c];
    g_eb[k * CDIM + c] = __float2bfloat16(v);
    float ss = v * v;
    #pragma unroll
    for (int off = 16; off > 0; off >>= 1)
        ss += __shfl_xor_sync(0xFFFFFFFFu, ss, off);
    __shared__ float part[8];
    if ((c & 31) == 0) part[c >> 5] = ss;
    __syncthreads();
    if (c == 0) {
        float t = 0.0f;
        #pragma unroll
        for (int i = 0; i < 8; i++) t += part[i];
        g_enf[k] = t;
    }
}

// --------------------------- 2) queue reset ----------------------------------
__global__ void k_zero() { g_qcnt = 0; }

// --------------------------- 3) GEMM + argmin + final filter -----------------
__global__ void __launch_bounds__(256, 2)
k_gemm_argmin(const float* __restrict__ x) {
    extern __shared__ char sm[];
    float* ensh  = (float*)(sm + OFF_EN);
    int*   scnt  = (int*)(sm + OFF_CNT);
    float* rmin2 = (float*)(sm + OFF_RMIN2);
    int*   qslot = (int*)(sm + OFF_QSLOT);
    __nv_bfloat16* zsh = (__nv_bfloat16*)(sm + OFF_Z);

    const int tid = threadIdx.x;
    const int n0  = blockIdx.x * BM;
    const int bb  = n0 >> 10;
    const int hw0 = n0 & 1023;

    if (tid < BM) scnt[tid] = 0;
    for (int i = tid; i < KCODE; i += 256) ensh[i] = g_enf[i];

    const uint32_t zbase = sptr(sm + OFF_Z);
    const uint32_t ebase = sptr(sm + OFF_E);

    // ---- B chunk loader: single buffer, one commit group per chunk ----
    auto loadB = [&](int ck) {
        const char* src = (const char*)g_eb + (size_t)ck * BN * 512;
        #pragma unroll
        for (int i = 0; i < 8; i++) {
            int t = tid + i * 256;
            int r = t >> 5, s = t & 31;
            cp16(ebase + r * ZSB + s * 16, src + (size_t)r * 512 + s * 16);
        }
        asm volatile("cp.async.commit_group;");
    };
    loadB(0);

    // ---- z tile: coalesced loads, paired bf16x2 stores ----
    const float* xb = x + (size_t)bb * CDIM * HW + hw0;
    #pragma unroll 4
    for (int it = 0; it < 64; it++) {
        int p = tid + it * 256;
        int cp = p >> 7, i = p & 127;
        float v0 = xb[(size_t)(2 * cp) * HW + i];
        float v1 = xb[(size_t)(2 * cp + 1) * HW + i];
        *(__nv_bfloat162*)&zsh[i * ZS + 2 * cp] = __floats2bfloat162_rn(v0, v1);
    }

    const int lane = tid & 31, wid = tid >> 5;
    const int qr = lane >> 2, qc = lane & 3;
    const int wm = wid & 3, wn = wid >> 2;          // 4x2 warp grid

    // ldmatrix lane address offsets (bytes)
    const uint32_t aoff = (uint32_t)(wm * 32 + (lane & 7) + ((lane >> 3) & 1) * 8) * ZSB
                        + ((lane >> 4) & 1) * 16;
    const uint32_t boff = (uint32_t)(wn * 32 + (lane & 7) + ((lane >> 4) & 1) * 8) * ZSB
                        + ((lane >> 3) & 1) * 16;

    float rm[4] = {3.0e38f, 3.0e38f, 3.0e38f, 3.0e38f};   // per (mt,h)

    for (int ck = 0; ck < NCHUNK; ck++) {
        asm volatile("cp.async.wait_group 0;");
        __syncthreads();                 // B(ck) visible (z tile too at ck=0)

        float acc[2][4][4];
        #pragma unroll
        for (int mt = 0; mt < 2; mt++)
            #pragma unroll
            for (int nt = 0; nt < 4; nt++)
                #pragma unroll
                for (int i = 0; i < 4; i++) acc[mt][nt][i] = 0.0f;

        #pragma unroll
        for (int kk = 0; kk < 16; kk++) {
            uint32_t afr[2][4];
            ldsm_x4(afr[0], zbase + aoff + kk * 32);
            ldsm_x4(afr[1], zbase + aoff + 16 * ZSB + kk * 32);
            uint32_t bfr[2][4];
            ldsm_x4(bfr[0], ebase + boff + kk * 32);
            ldsm_x4(bfr[1], ebase + boff + 16 * ZSB + kk * 32);
            #pragma unroll
            for (int mt = 0; mt < 2; mt++)
                #pragma unroll
                for (int p = 0; p < 2; p++) {
                    mma16816(acc[mt][2 * p + 0], afr[mt], &bfr[p][0]);
                    mma16816(acc[mt][2 * p + 1], afr[mt], &bfr[p][2]);
                }
        }
        __syncthreads();                 // all warps done reading B(ck)
        if (ck + 1 < NCHUNK) loadB(ck + 1);   // overlaps with epilogue

        // ---- pass 1: scores in place + per-(mt,h) running min ----
        float m[4] = {3.0e38f, 3.0e38f, 3.0e38f, 3.0e38f};
        #pragma unroll
        for (int mt = 0; mt < 2; mt++)
            #pragma unroll
            for (int nt = 0; nt < 4; nt++) {
                float en0 = ensh[ck * BN + wn * 32 + nt * 8 + 2 * qc + 0];
                float en1 = ensh[ck * BN + wn * 32 + nt * 8 + 2 * qc + 1];
                acc[mt][nt][0] = en0 - 2.0f * acc[mt][nt][0];
                acc[mt][nt][1] = en1 - 2.0f * acc[mt][nt][1];
                acc[mt][nt][2] = en0 - 2.0f * acc[mt][nt][2];
                acc[mt][nt][3] = en1 - 2.0f * acc[mt][nt][3];
                m[mt * 2 + 0] = fminf(m[mt * 2 + 0], fminf(acc[mt][nt][0], acc[mt][nt][1]));
                m[mt * 2 + 1] = fminf(m[mt * 2 + 1], fminf(acc[mt][nt][2], acc[mt][nt][3]));
            }
        #pragma unroll
        for (int s = 0; s < 4; s++) {
            m[s] = fminf(m[s], __shfl_xor_sync(0xFFFFFFFFu, m[s], 1));
            m[s] = fminf(m[s], __shfl_xor_sync(0xFFFFFFFFu, m[s], 2));
            rm[s] = fminf(rm[s], m[s]);
        }

        // ---- pass 2: rare pushes of (score, idx) to global slots ----
        #pragma unroll
        for (int mt = 0; mt < 2; mt++)
            #pragma unroll
            for (int h = 0; h < 2; h++) {
                const float thr = rm[mt * 2 + h] + MARGIN;
                const int row = wm * 32 + mt * 16 + h * 8 + qr;
                #pragma unroll
                for (int nt = 0; nt < 4; nt++)
                    #pragma unroll
                    for (int j = 0; j < 2; j++) {
                        float sc = acc[mt][nt][h * 2 + j];
                        if (sc <= thr) {
                            int kg = ck * BN + wn * 32 + nt * 8 + 2 * qc + j;
                            int p = atomicAdd(&scnt[row], 1);
                            if (p < CAP) {
                                g_csv[(size_t)(n0 + row) * CAP + p] = sc;
                                g_civ[(size_t)(n0 + row) * CAP + p] = kg;
                            }
                        }
                    }
            }
    }

    // ---- publish per-row per-half final mins ----
    if (qc == 0) {
        #pragma unroll
        for (int s = 0; s < 4; s++) {
            int row = wm * 32 + (s >> 1) * 16 + (s & 1) * 8 + qr;
            rmin2[row * 2 + wn] = rm[s];
        }
    }
    __syncthreads();

    // ---- final filter + classify (128 threads, one row each) ----
    if (tid < BM) {
        int t = tid, n = n0 + t;
        int cnt = scnt[t];
        if (cnt > CAP) {                         // overflow: full-scan fallback
            int q = atomicAdd(&g_qcnt, 1);
            qslot[t] = q; g_qn[q] = n; g_qc[q] = KCODE;
        } else {
            float thr = fminf(rmin2[t * 2], rmin2[t * 2 + 1]) + FMARGIN;
            int surv = 0, uniq = 0;
            for (int i = 0; i < cnt; i++)
                if (g_csv[(size_t)n * CAP + i] <= thr) { surv++; uniq = g_civ[(size_t)n * CAP + i]; }
            if (surv == 1) {
                g_best[n] = uniq; qslot[t] = -1;
            } else {
                int q = atomicAdd(&g_qcnt, 1);
                qslot[t] = q; g_qn[q] = n; g_qc[q] = surv;
                int w = 0;
                for (int i = 0; i < cnt; i++)
                    if (g_csv[(size_t)n * CAP + i] <= thr)
                        g_qcd[(size_t)q * CAP + (w++)] = g_civ[(size_t)n * CAP + i];
            }
        }
    }
    __syncthreads();

    // ---- coalesced fp32 z export for queued rows ----
    {
        const int ei = tid & 127;          // hw row (consecutive within warp)
        const int ch = tid >> 7;           // channel phase
        int q = qslot[ei];
        if (q >= 0 && q < MAXQ) {
            #pragma unroll 4
            for (int cc = 0; cc < 128; cc++) {
                int c = cc * 2 + ch;
                g_zq[(size_t)q * CDIM + c] = xb[(size_t)c * HW + ei];
            }
        }
    }
}

// --------------------------- 4) fp64 exact rescore ---------------------------
__global__ void k_rescore(const float* __restrict__ x, const float* __restrict__ e) {
    const int lane = threadIdx.x & 31;
    const int wglob = (blockIdx.x * blockDim.x + threadIdx.x) >> 5;
    const int nwarps = (gridDim.x * blockDim.x) >> 5;
    const int q = g_qcnt;

    for (int it = wglob; it < q; it += nwarps) {
        int n = g_qn[it];
        float z[8];
        if (it < MAXQ) {
            #pragma unroll
            for (int j = 0; j < 8; j++) z[j] = g_zq[(size_t)it * CDIM + lane + 32 * j];
        } else {
            int bb = n >> 10, hw = n & 1023;
            const float* xp = x + (size_t)bb * CDIM * HW + hw;
            #pragma unroll
            for (int j = 0; j < 8; j++) z[j] = xp[(size_t)(lane + 32 * j) * HW];
        }

        int cnt = g_qc[it];
        double bestS = 1e300;
        int bestK = 0x7FFFFFFF;
        const bool full = (cnt >= KCODE);
        const int iters = full ? KCODE : cnt;
        for (int i = 0; i < iters; i++) {
            int k = full ? i : g_qcd[(size_t)it * CAP + i];
            const float* er = e + (size_t)k * CDIM;
            double d = 0.0, en = 0.0;
            #pragma unroll
            for (int j = 0; j < 8; j++) {
                double ev = (double)er[lane + 32 * j];
                d  += (double)z[j] * ev;
                en += ev * ev;
            }
            #pragma unroll
            for (int off = 16; off > 0; off >>= 1) {
                d  += __shfl_xor_sync(0xFFFFFFFFu, d, off);
                en += __shfl_xor_sync(0xFFFFFFFFu, en, off);
            }
            double s = en - 2.0 * d;
            if (s < bestS || (s == bestS && k < bestK)) { bestS = s; bestK = k; }
        }
        if (lane == 0) g_best[n] = bestK;
    }
}

// --------------------------- 5) gather ---------------------------------------
__global__ void k_gather(const float* __restrict__ e, float* __restrict__ out) {
    extern __shared__ float gsm[];
    float* rows = gsm;                       // [GROWS][GSTRIDE]
    int*   sidx = (int*)(gsm + GROWS * GSTRIDE);
    const int tid = threadIdx.x, lane = tid & 31, wid = tid >> 5;
    const int n0 = blockIdx.x * GROWS;
    const int bb = n0 >> 10, hw0 = n0 & 1023;

    if (tid < GROWS) sidx[tid] = g_best[n0 + tid];
    __syncthreads();

    for (int v = wid; v < GROWS; v += 8) {
        const float* er = e + (size_t)sidx[v] * CDIM;
        #pragma unroll
        for (int j = 0; j < 8; j++)
            rows[v * GSTRIDE + lane + 32 * j] = er[lane + 32 * j];
    }
    __syncthreads();

    for (int c = wid; c < CDIM; c += 8) {
        float2 v;
        v.x = rows[(2 * lane + 0) * GSTRIDE + c];
        v.y = rows[(2 * lane + 1) * GSTRIDE + c];
        *(float2*)&out[((size_t)bb * CDIM + c) * HW + hw0 + 2 * lane] = v;
    }
}

// --------------------------- launch ------------------------------------------
extern "C" void kernel_launch(void* const* d_in, const int* in_sizes, int n_in,
                              void* d_out, int out_size) {
    const float* x = (const float*)d_in[0];
    const float* e = (const float*)d_in[1];
    if (n_in >= 2 && in_sizes[0] == KCODE * CDIM) {  // robust to input order
        x = (const float*)d_in[1];
        e = (const float*)d_in[0];
    }
    float* out = (float*)d_out;

    cudaFuncSetAttribute(k_gemm_argmin, cudaFuncAttributeMaxDynamicSharedMemorySize,
                         SMEM_TOTAL);
    cudaFuncSetAttribute(k_gather, cudaFuncAttributeMaxDynamicSharedMemorySize,
                         GATHER_SMEM);

    k_prep_e<<<KCODE, CDIM>>>(e);
    k_zero<<<1, 1>>>();
    k_gemm_argmin<<<NVEC / BM, 256, SMEM_TOTAL>>>(x);
    k_rescore<<<296, 256>>>(x, e);
    k_gather<<<NVEC / GROWS, 256, GATHER_SMEM>>>(e, out);
}

// round 14
// speedup vs baseline: 2.0196x; 2.0196x over previous
#include <cuda_runtime.h>
#include <cuda_bf16.h>
#include <cstdint>

// ============================================================================
// VQ quantizer: for each of N=131072 vectors z (C=256), argmin_k over K=512
// codes of ||z-e_k||^2, output e[argmin] in [B,C,H,W] layout.
//
//   1) prep_e:  e fp32 -> bf16 codebook + fp32 ||e_k||^2
//   2) zero:    reset rescore queue counter
//   3) gemm:    bf16 mma.sync GEMM, 4x2 warp grid, SHARED cross-warp row-min
//               (smem atomicMin, ordered-uint float) -> tight margins,
//               final filter, inline classify, coalesced z export. 2 CTAs/SM.
//   4) rescore: fp64 exact scores for ambiguous rows (coalesced z reads)
//   5) gather:  out[b,c,h,w] = e[best[n]][c], 64-row blocks, float2 stores
// ============================================================================

#define BATCH 128
#define CDIM  256
#define HW    1024
#define NVEC  (BATCH * HW)
#define KCODE 512
#define CAP   16
#define MARGIN  2.0f
#define FMARGIN 1.5f
#define MAXQ  49152

#define BM 128
#define BN 64
#define NCHUNK (KCODE / BN)
#define ZS  264                 // bf16 elements per smem row (256 + 8 pad)
#define ZSB 528                 // bytes per smem row

// smem byte offsets (102.5 KB -> 2 CTAs/SM)
#define OFF_EN    0                        // 512 f32   -> 2048
#define OFF_CNT   2048                     // 128 i32   -> 2560
#define OFF_RMINU 2560                     // 128 u32   -> 3072
#define OFF_QSLOT 3072                     // 128 i32   -> 3584
#define OFF_Z     3584                     // 128*528   -> 71168
#define OFF_E     71168                    // 64*528    -> 104960
#define SMEM_TOTAL 104960

#define GROWS 64                           // gather rows per block
#define GSTRIDE 257
#define GATHER_SMEM (GROWS * GSTRIDE * 4 + GROWS * 4)

// --------------------------- scratch (device globals) -----------------------
__device__ __nv_bfloat16 g_eb[KCODE * CDIM];
__device__ float         g_enf[KCODE];
__device__ int           g_best[NVEC];
__device__ float         g_csv[(size_t)NVEC * CAP];
__device__ int           g_civ[(size_t)NVEC * CAP];
__device__ int           g_qn[NVEC];
__device__ int           g_qc[NVEC];
__device__ int           g_qcd[(size_t)NVEC * CAP];
__device__ float         g_zq[(size_t)MAXQ * CDIM];
__device__ int           g_qcnt;

// --------------------------- helpers -----------------------------------------
__device__ __forceinline__ uint32_t sptr(const void* p) {
    return (uint32_t)__cvta_generic_to_shared(p);
}
__device__ __forceinline__ void cp16(uint32_t dst, const void* src) {
    asm volatile("cp.async.cg.shared.global [%0], [%1], 16;" :: "r"(dst), "l"(src));
}
__device__ __forceinline__ void ldsm_x4(uint32_t* d, uint32_t addr) {
    asm volatile("ldmatrix.sync.aligned.m8n8.x4.shared.b16 {%0,%1,%2,%3}, [%4];"
                 : "=r"(d[0]), "=r"(d[1]), "=r"(d[2]), "=r"(d[3]) : "r"(addr));
}
__device__ __forceinline__ void mma16816(float* c, const uint32_t* a, const uint32_t* b) {
    asm volatile(
        "mma.sync.aligned.m16n8k16.row.col.f32.bf16.bf16.f32 "
        "{%0,%1,%2,%3}, {%4,%5,%6,%7}, {%8,%9}, {%0,%1,%2,%3};"
        : "+f"(c[0]), "+f"(c[1]), "+f"(c[2]), "+f"(c[3])
        : "r"(a[0]), "r"(a[1]), "r"(a[2]), "r"(a[3]), "r"(b[0]), "r"(b[1]));
}
// monotone float <-> ordered-uint mapping (for atomicMin on scores)
__device__ __forceinline__ uint32_t fpack(float f) {
    uint32_t u = __float_as_uint(f);
    return (u & 0x80000000u) ? ~u : (u | 0x80000000u);
}
__device__ __forceinline__ float funpack(uint32_t u) {
    return (u & 0x80000000u) ? __uint_as_float(u & 0x7FFFFFFFu)
                             : __uint_as_float(~u);
}

// --------------------------- 1) codebook prep --------------------------------
__global__ void k_prep_e(const float* __restrict__ e) {
    int k = blockIdx.x, c = threadIdx.x;
    float v = e[k * CDIM + c];
    g_eb[k * CDIM + c] = __float2bfloat16(v);
    float ss = v * v;
    #pragma unroll
    for (int off = 16; off > 0; off >>= 1)
        ss += __shfl_xor_sync(0xFFFFFFFFu, ss, off);
    __shared__ float part[8];
    if ((c & 31) == 0) part[c >> 5] = ss;
    __syncthreads();
    if (c == 0) {
        float t = 0.0f;
        #pragma unroll
        for (int i = 0; i < 8; i++) t += part[i];
        g_enf[k] = t;
    }
}

// --------------------------- 2) queue reset ----------------------------------
__global__ void k_zero() { g_qcnt = 0; }

// --------------------------- 3) GEMM + argmin + final filter -----------------
__global__ void __launch_bounds__(256, 2)
k_gemm_argmin(const float* __restrict__ x) {
    extern __shared__ char sm[];
    float*    ensh   = (float*)(sm + OFF_EN);
    int*      scnt   = (int*)(sm + OFF_CNT);
    uint32_t* rowminu= (uint32_t*)(sm + OFF_RMINU);
    int*      qslot  = (int*)(sm + OFF_QSLOT);
    __nv_bfloat16* zsh = (__nv_bfloat16*)(sm + OFF_Z);

    const int tid = threadIdx.x;
    const int n0  = blockIdx.x * BM;
    const int bb  = n0 >> 10;
    const int hw0 = n0 & 1023;

    if (tid < BM) { scnt[tid] = 0; rowminu[tid] = 0xFFFFFFFFu; }
    for (int i = tid; i < KCODE; i += 256) ensh[i] = g_enf[i];

    const uint32_t zbase = sptr(sm + OFF_Z);
    const uint32_t ebase = sptr(sm + OFF_E);

    // ---- B chunk loader: single buffer, one commit group per chunk ----
    auto loadB = [&](int ck) {
        const char* src = (const char*)g_eb + (size_t)ck * BN * 512;
        #pragma unroll
        for (int i = 0; i < 8; i++) {
            int t = tid + i * 256;
            int r = t >> 5, s = t & 31;
            cp16(ebase + r * ZSB + s * 16, src + (size_t)r * 512 + s * 16);
        }
        asm volatile("cp.async.commit_group;");
    };
    loadB(0);

    // ---- z tile: coalesced loads, paired bf16x2 stores ----
    const float* xb = x + (size_t)bb * CDIM * HW + hw0;
    #pragma unroll 4
    for (int it = 0; it < 64; it++) {
        int p = tid + it * 256;
        int cp = p >> 7, i = p & 127;
        float v0 = xb[(size_t)(2 * cp) * HW + i];
        float v1 = xb[(size_t)(2 * cp + 1) * HW + i];
        *(__nv_bfloat162*)&zsh[i * ZS + 2 * cp] = __floats2bfloat162_rn(v0, v1);
    }

    const int lane = tid & 31, wid = tid >> 5;
    const int qr = lane >> 2, qc = lane & 3;
    const int wm = wid & 3, wn = wid >> 2;          // 4x2 warp grid

    // ldmatrix lane address offsets (bytes)
    const uint32_t aoff = (uint32_t)(wm * 32 + (lane & 7) + ((lane >> 3) & 1) * 8) * ZSB
                        + ((lane >> 4) & 1) * 16;
    const uint32_t boff = (uint32_t)(wn * 32 + (lane & 7) + ((lane >> 4) & 1) * 8) * ZSB
                        + ((lane >> 3) & 1) * 16;

    for (int ck = 0; ck < NCHUNK; ck++) {
        asm volatile("cp.async.wait_group 0;");
        __syncthreads();                 // B(ck) visible (z tile too at ck=0)

        float acc[2][4][4];
        #pragma unroll
        for (int mt = 0; mt < 2; mt++)
            #pragma unroll
            for (int nt = 0; nt < 4; nt++)
                #pragma unroll
                for (int i = 0; i < 4; i++) acc[mt][nt][i] = 0.0f;

        #pragma unroll
        for (int kk = 0; kk < 16; kk++) {
            uint32_t afr[2][4];
            ldsm_x4(afr[0], zbase + aoff + kk * 32);
            ldsm_x4(afr[1], zbase + aoff + 16 * ZSB + kk * 32);
            uint32_t bfr[2][4];
            ldsm_x4(bfr[0], ebase + boff + kk * 32);
            ldsm_x4(bfr[1], ebase + boff + 16 * ZSB + kk * 32);
            #pragma unroll
            for (int mt = 0; mt < 2; mt++)
                #pragma unroll
                for (int p = 0; p < 2; p++) {
                    mma16816(acc[mt][2 * p + 0], afr[mt], &bfr[p][0]);
                    mma16816(acc[mt][2 * p + 1], afr[mt], &bfr[p][2]);
                }
        }
        __syncthreads();                 // all warps done reading B(ck)
        if (ck + 1 < NCHUNK) loadB(ck + 1);   // overlaps with epilogue

        // ---- pass 1: scores in place + per-(mt,h) local min ----
        float m[4] = {3.0e38f, 3.0e38f, 3.0e38f, 3.0e38f};
        #pragma unroll
        for (int mt = 0; mt < 2; mt++)
            #pragma unroll
            for (int nt = 0; nt < 4; nt++) {
                float en0 = ensh[ck * BN + wn * 32 + nt * 8 + 2 * qc + 0];
                float en1 = ensh[ck * BN + wn * 32 + nt * 8 + 2 * qc + 1];
                acc[mt][nt][0] = en0 - 2.0f * acc[mt][nt][0];
                acc[mt][nt][1] = en1 - 2.0f * acc[mt][nt][1];
                acc[mt][nt][2] = en0 - 2.0f * acc[mt][nt][2];
                acc[mt][nt][3] = en1 - 2.0f * acc[mt][nt][3];
                m[mt * 2 + 0] = fminf(m[mt * 2 + 0], fminf(acc[mt][nt][0], acc[mt][nt][1]));
                m[mt * 2 + 1] = fminf(m[mt * 2 + 1], fminf(acc[mt][nt][2], acc[mt][nt][3]));
            }
        #pragma unroll
        for (int s = 0; s < 4; s++) {
            m[s] = fminf(m[s], __shfl_xor_sync(0xFFFFFFFFu, m[s], 1));
            m[s] = fminf(m[s], __shfl_xor_sync(0xFFFFFFFFu, m[s], 2));
        }
        // ---- merge into shared per-row running min (both halves combine) ----
        if (qc == 0) {
            #pragma unroll
            for (int s = 0; s < 4; s++) {
                int row = wm * 32 + (s >> 1) * 16 + (s & 1) * 8 + qr;
                atomicMin(&rowminu[row], fpack(m[s]));
            }
        }
        __syncthreads();                 // combined row mins visible to all

        // ---- pass 2: rare pushes of (score, idx) vs TIGHT threshold ----
        #pragma unroll
        for (int mt = 0; mt < 2; mt++)
            #pragma unroll
            for (int h = 0; h < 2; h++) {
                const int row = wm * 32 + mt * 16 + h * 8 + qr;
                const float thr = funpack(rowminu[row]) + MARGIN;
                #pragma unroll
                for (int nt = 0; nt < 4; nt++)
                    #pragma unroll
                    for (int j = 0; j < 2; j++) {
                        float sc = acc[mt][nt][h * 2 + j];
                        if (sc <= thr) {
                            int kg = ck * BN + wn * 32 + nt * 8 + 2 * qc + j;
                            int p = atomicAdd(&scnt[row], 1);
                            if (p < CAP) {
                                g_csv[(size_t)(n0 + row) * CAP + p] = sc;
                                g_civ[(size_t)(n0 + row) * CAP + p] = kg;
                            }
                        }
                    }
            }
    }
    __syncthreads();

    // ---- final filter + classify (128 threads, one row each) ----
    if (tid < BM) {
        int t = tid, n = n0 + t;
        int cnt = scnt[t];
        if (cnt > CAP) {                         // overflow: full-scan fallback
            int q = atomicAdd(&g_qcnt, 1);
            qslot[t] = q; g_qn[q] = n; g_qc[q] = KCODE;
        } else {
            float thr = funpack(rowminu[t]) + FMARGIN;
            int surv = 0, uniq = 0;
            for (int i = 0; i < cnt; i++)
                if (g_csv[(size_t)n * CAP + i] <= thr) { surv++; uniq = g_civ[(size_t)n * CAP + i]; }
            if (surv == 1) {
                g_best[n] = uniq; qslot[t] = -1;
            } else {
                int q = atomicAdd(&g_qcnt, 1);
                qslot[t] = q; g_qn[q] = n; g_qc[q] = surv;
                int w = 0;
                for (int i = 0; i < cnt; i++)
                    if (g_csv[(size_t)n * CAP + i] <= thr)
                        g_qcd[(size_t)q * CAP + (w++)] = g_civ[(size_t)n * CAP + i];
            }
        }
    }
    __syncthreads();

    // ---- coalesced fp32 z export for queued rows ----
    {
        const int ei = tid & 127;          // hw row (consecutive within warp)
        const int ch = tid >> 7;           // channel phase
        int q = qslot[ei];
        if (q >= 0 && q < MAXQ) {
            #pragma unroll 4
            for (int cc = 0; cc < 128; cc++) {
                int c = cc * 2 + ch;
                g_zq[(size_t)q * CDIM + c] = xb[(size_t)c * HW + ei];
            }
        }
    }
}

// --------------------------- 4) fp64 exact rescore ---------------------------
__global__ void k_rescore(const float* __restrict__ x, const float* __restrict__ e) {
    const int lane = threadIdx.x & 31;
    const int wglob = (blockIdx.x * blockDim.x + threadIdx.x) >> 5;
    const int nwarps = (gridDim.x * blockDim.x) >> 5;
    const int q = g_qcnt;

    for (int it = wglob; it < q; it += nwarps) {
        int n = g_qn[it];
        float z[8];
        if (it < MAXQ) {
            #pragma unroll
            for (int j = 0; j < 8; j++) z[j] = g_zq[(size_t)it * CDIM + lane + 32 * j];
        } else {
            int bb = n >> 10, hw = n & 1023;
            const float* xp = x + (size_t)bb * CDIM * HW + hw;
            #pragma unroll
            for (int j = 0; j < 8; j++) z[j] = xp[(size_t)(lane + 32 * j) * HW];
        }

        int cnt = g_qc[it];
        double bestS = 1e300;
        int bestK = 0x7FFFFFFF;
        const bool full = (cnt >= KCODE);
        const int iters = full ? KCODE : cnt;
        for (int i = 0; i < iters; i++) {
            int k = full ? i : g_qcd[(size_t)it * CAP + i];
            const float* er = e + (size_t)k * CDIM;
            double d = 0.0, en = 0.0;
            #pragma unroll
            for (int j = 0; j < 8; j++) {
                double ev = (double)er[lane + 32 * j];
                d  += (double)z[j] * ev;
                en += ev * ev;
            }
            #pragma unroll
            for (int off = 16; off > 0; off >>= 1) {
                d  += __shfl_xor_sync(0xFFFFFFFFu, d, off);
                en += __shfl_xor_sync(0xFFFFFFFFu, en, off);
            }
            double s = en - 2.0 * d;
            if (s < bestS || (s == bestS && k < bestK)) { bestS = s; bestK = k; }
        }
        if (lane == 0) g_best[n] = bestK;
    }
}

// --------------------------- 5) gather ---------------------------------------
__global__ void k_gather(const float* __restrict__ e, float* __restrict__ out) {
    extern __shared__ float gsm[];
    float* rows = gsm;                       // [GROWS][GSTRIDE]
    int*   sidx = (int*)(gsm + GROWS * GSTRIDE);
    const int tid = threadIdx.x, lane = tid & 31, wid = tid >> 5;
    const int n0 = blockIdx.x * GROWS;
    const int bb = n0 >> 10, hw0 = n0 & 1023;

    if (tid < GROWS) sidx[tid] = g_best[n0 + tid];
    __syncthreads();

    for (int v = wid; v < GROWS; v += 8) {
        const float* er = e + (size_t)sidx[v] * CDIM;
        #pragma unroll
        for (int j = 0; j < 8; j++)
            rows[v * GSTRIDE + lane + 32 * j] = er[lane + 32 * j];
    }
    __syncthreads();

    for (int c = wid; c < CDIM; c += 8) {
        float2 v;
        v.x = rows[(2 * lane + 0) * GSTRIDE + c];
        v.y = rows[(2 * lane + 1) * GSTRIDE + c];
        *(float2*)&out[((size_t)bb * CDIM + c) * HW + hw0 + 2 * lane] = v;
    }
}

// --------------------------- launch ------------------------------------------
extern "C" void kernel_launch(void* const* d_in, const int* in_sizes, int n_in,
                              void* d_out, int out_size) {
    const float* x = (const float*)d_in[0];
    const float* e = (const float*)d_in[1];
    if (n_in >= 2 && in_sizes[0] == KCODE * CDIM) {  // robust to input order
        x = (const float*)d_in[1];
        e = (const float*)d_in[0];
    }
    float* out = (float*)d_out;

    cudaFuncSetAttribute(k_gemm_argmin, cudaFuncAttributeMaxDynamicSharedMemorySize,
                         SMEM_TOTAL);
    cudaFuncSetAttribute(k_gather, cudaFuncAttributeMaxDynamicSharedMemorySize,
                         GATHER_SMEM);

    k_prep_e<<<KCODE, CDIM>>>(e);
    k_zero<<<1, 1>>>();
    k_gemm_argmin<<<NVEC / BM, 256, SMEM_TOTAL>>>(x);
    k_rescore<<<296, 256>>>(x, e);
    k_gather<<<NVEC / GROWS, 256, GATHER_SMEM>>>(e, out);
}

// round 16
// speedup vs baseline: 2.1061x; 1.0428x over previous
#include <cuda_runtime.h>
#include <cuda_bf16.h>
#include <cstdint>

// ============================================================================
// VQ quantizer: for each of N=131072 vectors z (C=256), argmin_k over K=512
// codes of ||z-e_k||^2, output e[argmin] in [B,C,H,W] layout.
//
//   1) prep_e:  e fp32 -> bf16 codebook + fp32 ||e_k||^2 (+ queue reset)
//   2) gemm:    bf16 mma.sync GEMM, 8x1 warp grid (16x64 tile/warp, exact
//               per-warp row min), margin candidates, final filter, inline
//               classify, coalesced z export. 2 CTAs/SM, single-buffer B.
//   3) rescore: fp64 exact scores for ambiguous rows (coalesced z reads)
//   4) gather:  out[b,c,h,w] = e[best[n]][c], 64-row blocks, float2 stores
// ============================================================================

#define BATCH 128
#define CDIM  256
#define HW    1024
#define NVEC  (BATCH * HW)
#define KCODE 512
#define CAP   16
#define MARGIN  2.0f      // per-chunk collection margin (validated)
#define FMARGIN 1.5f      // final filter margin (validated)
#define MAXQ  49152

#define BM 128
#define BN 64
#define NCHUNK (KCODE / BN)
#define ZS  264                 // bf16 elements per smem row (256 + 8 pad)
#define ZSB 528                 // bytes per smem row

// smem byte offsets (102.5 KB total -> 2 CTAs/SM)
#define OFF_EN    0                        // 512 f32   -> 2048
#define OFF_CNT   2048                     // 128 i32   -> 2560
#define OFF_RMIN  2560                     // 128 f32   -> 3072
#define OFF_QSLOT 3072                     // 128 i32   -> 3584
#define OFF_Z     3584                     // 128*528   -> 71168
#define OFF_E     71168                    // 64*528    -> 104960
#define SMEM_TOTAL 104960

#define GROWS 64                           // gather rows per block
#define GSTRIDE 257
#define GATHER_SMEM (GROWS * GSTRIDE * 4 + GROWS * 4)

// --------------------------- scratch (device globals) -----------------------
__device__ __nv_bfloat16 g_eb[KCODE * CDIM];
__device__ float         g_enf[KCODE];
__device__ int           g_best[NVEC];
__device__ float         g_csv[(size_t)NVEC * CAP];   // candidate scores
__device__ int           g_civ[(size_t)NVEC * CAP];   // candidate indices
__device__ int           g_qn[NVEC];
__device__ int           g_qc[NVEC];
__device__ int           g_qcd[(size_t)NVEC * CAP];
__device__ float         g_zq[(size_t)MAXQ * CDIM];
__device__ int           g_qcnt;

// --------------------------- asm helpers -------------------------------------
__device__ __forceinline__ uint32_t sptr(const void* p) {
    return (uint32_t)__cvta_generic_to_shared(p);
}
__device__ __forceinline__ void cp16(uint32_t dst, const void* src) {
    asm volatile("cp.async.cg.shared.global [%0], [%1], 16;" :: "r"(dst), "l"(src));
}
__device__ __forceinline__ void ldsm_x4(uint32_t* d, uint32_t addr) {
    asm volatile("ldmatrix.sync.aligned.m8n8.x4.shared.b16 {%0,%1,%2,%3}, [%4];"
                 : "=r"(d[0]), "=r"(d[1]), "=r"(d[2]), "=r"(d[3]) : "r"(addr));
}
__device__ __forceinline__ void mma16816(float* c, const uint32_t* a, const uint32_t* b) {
    asm volatile(
        "mma.sync.aligned.m16n8k16.row.col.f32.bf16.bf16.f32 "
        "{%0,%1,%2,%3}, {%4,%5,%6,%7}, {%8,%9}, {%0,%1,%2,%3};"
        : "+f"(c[0]), "+f"(c[1]), "+f"(c[2]), "+f"(c[3])
        : "r"(a[0]), "r"(a[1]), "r"(a[2]), "r"(a[3]), "r"(b[0]), "r"(b[1]));
}

// --------------------------- 1) codebook prep (+queue reset) -----------------
__global__ void k_prep_e(const float* __restrict__ e) {
    int k = blockIdx.x, c = threadIdx.x;
    if (k == 0 && c == 0) g_qcnt = 0;
    float v = e[k * CDIM + c];
    g_eb[k * CDIM + c] = __float2bfloat16(v);
    float ss = v * v;
    #pragma unroll
    for (int off = 16; off > 0; off >>= 1)
        ss += __shfl_xor_sync(0xFFFFFFFFu, ss, off);
    __shared__ float part[8];
    if ((c & 31) == 0) part[c >> 5] = ss;
    __syncthreads();
    if (c == 0) {
        float t = 0.0f;
        #pragma unroll
        for (int i = 0; i < 8; i++) t += part[i];
        g_enf[k] = t;
    }
}

// --------------------------- 2) GEMM + argmin + final filter -----------------
__global__ void __launch_bounds__(256, 2)
k_gemm_argmin(const float* __restrict__ x) {
    extern __shared__ char sm[];
    float* ensh  = (float*)(sm + OFF_EN);
    int*   scnt  = (int*)(sm + OFF_CNT);
    float* rminsh= (float*)(sm + OFF_RMIN);
    int*   qslot = (int*)(sm + OFF_QSLOT);
    __nv_bfloat16* zsh = (__nv_bfloat16*)(sm + OFF_Z);

    const int tid = threadIdx.x;
    const int n0  = blockIdx.x * BM;
    const int bb  = n0 >> 10;
    const int hw0 = n0 & 1023;

    if (tid < BM) scnt[tid] = 0;
    for (int i = tid; i < KCODE; i += 256) ensh[i] = g_enf[i];

    const uint32_t zbase = sptr(sm + OFF_Z);
    const uint32_t ebase = sptr(sm + OFF_E);

    // ---- B chunk loader: single buffer, one commit group per chunk ----
    auto loadB = [&](int ck) {
        const char* src = (const char*)g_eb + (size_t)ck * BN * 512;
        #pragma unroll
        for (int i = 0; i < 8; i++) {
            int t = tid + i * 256;
            int r = t >> 5, s = t & 31;
            cp16(ebase + r * ZSB + s * 16, src + (size_t)r * 512 + s * 16);
        }
        asm volatile("cp.async.commit_group;");
    };
    loadB(0);   // prefetch chunk 0 behind the z-tile transpose

    // ---- z tile: coalesced loads, paired bf16x2 stores ----
    const float* xb = x + (size_t)bb * CDIM * HW + hw0;
    #pragma unroll 4
    for (int it = 0; it < 64; it++) {
        int p = tid + it * 256;
        int cp = p >> 7, i = p & 127;
        float v0 = xb[(size_t)(2 * cp) * HW + i];
        float v1 = xb[(size_t)(2 * cp + 1) * HW + i];
        *(__nv_bfloat162*)&zsh[i * ZS + 2 * cp] = __floats2bfloat162_rn(v0, v1);
    }

    const int lane = tid & 31, wid = tid >> 5;
    const int qr = lane >> 2, qc = lane & 3;
    const int rowbase = wid * 16;

    const uint32_t aoff = (uint32_t)(rowbase + (lane & 7) + ((lane >> 3) & 1) * 8) * ZSB
                        + ((lane >> 4) & 1) * 16;
    const uint32_t boff = (uint32_t)((lane & 7) + ((lane >> 4) & 1) * 8) * ZSB
                        + ((lane >> 3) & 1) * 16;

    float rmin0 = 3.0e38f, rmin1 = 3.0e38f;
    const int row0 = rowbase + qr, row1 = rowbase + 8 + qr;

    for (int ck = 0; ck < NCHUNK; ck++) {
        asm volatile("cp.async.wait_group 0;");
        __syncthreads();                 // B(ck) visible (z tile too at ck=0)

        float acc[8][4];
        #pragma unroll
        for (int nt = 0; nt < 8; nt++)
            #pragma unroll
            for (int i = 0; i < 4; i++) acc[nt][i] = 0.0f;

        #pragma unroll
        for (int kk = 0; kk < 16; kk++) {
            uint32_t afr[4];
            ldsm_x4(afr, zbase + aoff + kk * 32);
            uint32_t bfr[4][4];
            #pragma unroll
            for (int p = 0; p < 4; p++)
                ldsm_x4(bfr[p], ebase + boff + p * (16 * ZSB) + kk * 32);
            #pragma unroll
            for (int p = 0; p < 4; p++) {
                mma16816(acc[2 * p + 0], afr, &bfr[p][0]);
                mma16816(acc[2 * p + 1], afr, &bfr[p][2]);
            }
        }
        __syncthreads();                 // all warps done reading B(ck)
        if (ck + 1 < NCHUNK) loadB(ck + 1);   // overlaps with epilogue below

        // ---- pass 1: scores in place + exact running min ----
        float m0 = 3.0e38f, m1 = 3.0e38f;
        #pragma unroll
        for (int nt = 0; nt < 8; nt++) {
            float en0 = ensh[ck * BN + nt * 8 + 2 * qc + 0];
            float en1 = ensh[ck * BN + nt * 8 + 2 * qc + 1];
            acc[nt][0] = en0 - 2.0f * acc[nt][0];
            acc[nt][1] = en1 - 2.0f * acc[nt][1];
            acc[nt][2] = en0 - 2.0f * acc[nt][2];
            acc[nt][3] = en1 - 2.0f * acc[nt][3];
            m0 = fminf(m0, fminf(acc[nt][0], acc[nt][1]));
            m1 = fminf(m1, fminf(acc[nt][2], acc[nt][3]));
        }
        m0 = fminf(m0, __shfl_xor_sync(0xFFFFFFFFu, m0, 1));
        m0 = fminf(m0, __shfl_xor_sync(0xFFFFFFFFu, m0, 2));
        m1 = fminf(m1, __shfl_xor_sync(0xFFFFFFFFu, m1, 1));
        m1 = fminf(m1, __shfl_xor_sync(0xFFFFFFFFu, m1, 2));
        rmin0 = fminf(rmin0, m0);
        rmin1 = fminf(rmin1, m1);
        const float thr0 = rmin0 + MARGIN, thr1 = rmin1 + MARGIN;

        // ---- pass 2: rare pushes of (score, idx) to global slots ----
        #pragma unroll
        for (int nt = 0; nt < 8; nt++) {
            int kg = ck * BN + nt * 8 + 2 * qc;
            if (acc[nt][0] <= thr0) {
                int p = atomicAdd(&scnt[row0], 1);
                if (p < CAP) { g_csv[(size_t)(n0 + row0) * CAP + p] = acc[nt][0];
                               g_civ[(size_t)(n0 + row0) * CAP + p] = kg; }
            }
            if (acc[nt][1] <= thr0) {
                int p = atomicAdd(&scnt[row0], 1);
                if (p < CAP) { g_csv[(size_t)(n0 + row0) * CAP + p] = acc[nt][1];
                               g_civ[(size_t)(n0 + row0) * CAP + p] = kg + 1; }
            }
            if (acc[nt][2] <= thr1) {
                int p = atomicAdd(&scnt[row1], 1);
                if (p < CAP) { g_csv[(size_t)(n0 + row1) * CAP + p] = acc[nt][2];
                               g_civ[(size_t)(n0 + row1) * CAP + p] = kg; }
            }
            if (acc[nt][3] <= thr1) {
                int p = atomicAdd(&scnt[row1], 1);
                if (p < CAP) { g_csv[(size_t)(n0 + row1) * CAP + p] = acc[nt][3];
                               g_civ[(size_t)(n0 + row1) * CAP + p] = kg + 1; }
            }
        }
    }

    // ---- publish per-row final mins ----
    if (qc == 0) { rminsh[row0] = rmin0; rminsh[row1] = rmin1; }
    __syncthreads();

    // ---- final filter + classify (128 threads, one row each) ----
    if (tid < BM) {
        int t = tid, n = n0 + t;
        int cnt = scnt[t];
        if (cnt > CAP) {                         // overflow: full-scan fallback
            int q = atomicAdd(&g_qcnt, 1);
            qslot[t] = q; g_qn[q] = n; g_qc[q] = KCODE;
        } else {
            float thr = rminsh[t] + FMARGIN;
            int surv = 0, uniq = 0;
            for (int i = 0; i < cnt; i++)
                if (g_csv[(size_t)n * CAP + i] <= thr) { surv++; uniq = g_civ[(size_t)n * CAP + i]; }
            if (surv == 1) {
                g_best[n] = uniq; qslot[t] = -1;
            } else {
                int q = atomicAdd(&g_qcnt, 1);
                qslot[t] = q; g_qn[q] = n; g_qc[q] = surv;
                int w = 0;
                for (int i = 0; i < cnt; i++)
                    if (g_csv[(size_t)n * CAP + i] <= thr)
                        g_qcd[(size_t)q * CAP + (w++)] = g_civ[(size_t)n * CAP + i];
            }
        }
    }
    __syncthreads();

    // ---- coalesced fp32 z export for queued rows ----
    {
        const int ei = tid & 127;          // hw row (consecutive within warp)
        const int ch = tid >> 7;           // channel phase
        int q = qslot[ei];
        if (q >= 0 && q < MAXQ) {
            #pragma unroll 4
            for (int cc = 0; cc < 128; cc++) {
                int c = cc * 2 + ch;
                g_zq[(size_t)q * CDIM + c] = xb[(size_t)c * HW + ei];
            }
        }
    }
}

// --------------------------- 3) fp64 exact rescore ---------------------------
__global__ void k_rescore(const float* __restrict__ x, const float* __restrict__ e) {
    const int lane = threadIdx.x & 31;
    const int wglob = (blockIdx.x * blockDim.x + threadIdx.x) >> 5;
    const int nwarps = (gridDim.x * blockDim.x) >> 5;
    const int q = g_qcnt;

    for (int it = wglob; it < q; it += nwarps) {
        int n = g_qn[it];
        float z[8];
        if (it < MAXQ) {
            #pragma unroll
            for (int j = 0; j < 8; j++) z[j] = g_zq[(size_t)it * CDIM + lane + 32 * j];
        } else {   // export overflow: strided read from x
            int bb = n >> 10, hw = n & 1023;
            const float* xp = x + (size_t)bb * CDIM * HW + hw;
            #pragma unroll
            for (int j = 0; j < 8; j++) z[j] = xp[(size_t)(lane + 32 * j) * HW];
        }

        int cnt = g_qc[it];
        double bestS = 1e300;
        int bestK = 0x7FFFFFFF;
        const bool full = (cnt >= KCODE);
        const int iters = full ? KCODE : cnt;
        for (int i = 0; i < iters; i++) {
            int k = full ? i : g_qcd[(size_t)it * CAP + i];
            const float* er = e + (size_t)k * CDIM;
            double d = 0.0, en = 0.0;
            #pragma unroll
            for (int j = 0; j < 8; j++) {
                double ev = (double)er[lane + 32 * j];
                d  += (double)z[j] * ev;
                en += ev * ev;
            }
            #pragma unroll
            for (int off = 16; off > 0; off >>= 1) {
                d  += __shfl_xor_sync(0xFFFFFFFFu, d, off);
                en += __shfl_xor_sync(0xFFFFFFFFu, en, off);
            }
            double s = en - 2.0 * d;
            if (s < bestS || (s == bestS && k < bestK)) { bestS = s; bestK = k; }
        }
        if (lane == 0) g_best[n] = bestK;
    }
}

// --------------------------- 4) gather ---------------------------------------
__global__ void k_gather(const float* __restrict__ e, float* __restrict__ out) {
    extern __shared__ float gsm[];
    float* rows = gsm;                       // [GROWS][GSTRIDE]
    int*   sidx = (int*)(gsm + GROWS * GSTRIDE);
    const int tid = threadIdx.x, lane = tid & 31, wid = tid >> 5;
    const int n0 = blockIdx.x * GROWS;
    const int bb = n0 >> 10, hw0 = n0 & 1023;

    if (tid < GROWS) sidx[tid] = g_best[n0 + tid];
    __syncthreads();

    for (int v = wid; v < GROWS; v += 8) {
        const float* er = e + (size_t)sidx[v] * CDIM;
        #pragma unroll
        for (int j = 0; j < 8; j++)
            rows[v * GSTRIDE + lane + 32 * j] = er[lane + 32 * j];
    }
    __syncthreads();

    for (int c = wid; c < CDIM; c += 8) {
        float2 v;
        v.x = rows[(2 * lane + 0) * GSTRIDE + c];
        v.y = rows[(2 * lane + 1) * GSTRIDE + c];
        *(float2*)&out[((size_t)bb * CDIM + c) * HW + hw0 + 2 * lane] = v;
    }
}

// --------------------------- launch ------------------------------------------
extern "C" void kernel_launch(void* const* d_in, const int* in_sizes, int n_in,
                              void* d_out, int out_size) {
    const float* x = (const float*)d_in[0];
    const float* e = (const float*)d_in[1];
    if (n_in >= 2 && in_sizes[0] == KCODE * CDIM) {  // robust to input order
        x = (const float*)d_in[1];
        e = (const float*)d_in[0];
    }
    float* out = (float*)d_out;

    cudaFuncSetAttribute(k_gemm_argmin, cudaFuncAttributeMaxDynamicSharedMemorySize,
                         SMEM_TOTAL);
    cudaFuncSetAttribute(k_gather, cudaFuncAttributeMaxDynamicSharedMemorySize,
                         GATHER_SMEM);

    k_prep_e<<<KCODE, CDIM>>>(e);
    k_gemm_argmin<<<NVEC / BM, 256, SMEM_TOTAL>>>(x);
    k_rescore<<<296, 256>>>(x, e);
    k_gather<<<NVEC / GROWS, 256, GATHER_SMEM>>>(e, out);
}

// round 17
// speedup vs baseline: 2.1335x; 1.0130x over previous
#include <cuda_runtime.h>
#include <cuda_bf16.h>
#include <cstdint>

// ============================================================================
// VQ quantizer: for each of N=131072 vectors z (C=256), argmin_k over K=512
// codes of ||z-e_k||^2, output e[argmin] in [B,C,H,W] layout.
//
//   1) prep_e:  e fp32 -> bf16 codebook + fp32 ||e_k||^2 (+ queue reset)
//   2) gemm:    bf16 mma.sync GEMM, 8x1 warp grid (16x64 tile/warp, exact
//               per-warp row min), margin candidates, final filter, inline
//               classify, coalesced z export. 2 CTAs/SM, single-buffer B.
//   3) rescore: fp64 exact scores for ambiguous rows (coalesced z reads)
//   4) gather:  out[b,c,h,w] = e[best[n]][c], 32-row blocks, 512 threads
//               (static 33KB smem -> 4 CTAs/SM, 100% occupancy)
// ============================================================================

#define BATCH 128
#define CDIM  256
#define HW    1024
#define NVEC  (BATCH * HW)
#define KCODE 512
#define CAP   16
#define MARGIN  2.0f      // per-chunk collection margin (validated)
#define FMARGIN 1.5f      // final filter margin (validated)
#define MAXQ  49152

#define BM 128
#define BN 64
#define NCHUNK (KCODE / BN)
#define ZS  264                 // bf16 elements per smem row (256 + 8 pad)
#define ZSB 528                 // bytes per smem row

// smem byte offsets (102.5 KB total -> 2 CTAs/SM)
#define OFF_EN    0                        // 512 f32   -> 2048
#define OFF_CNT   2048                     // 128 i32   -> 2560
#define OFF_RMIN  2560                     // 128 f32   -> 3072
#define OFF_QSLOT 3072                     // 128 i32   -> 3584
#define OFF_Z     3584                     // 128*528   -> 71168
#define OFF_E     71168                    // 64*528    -> 104960
#define SMEM_TOTAL 104960

// --------------------------- scratch (device globals) -----------------------
__device__ __nv_bfloat16 g_eb[KCODE * CDIM];
__device__ float         g_enf[KCODE];
__device__ int           g_best[NVEC];
__device__ float         g_csv[(size_t)NVEC * CAP];   // candidate scores
__device__ int           g_civ[(size_t)NVEC * CAP];   // candidate indices
__device__ int           g_qn[NVEC];
__device__ int           g_qc[NVEC];
__device__ int           g_qcd[(size_t)NVEC * CAP];
__device__ float         g_zq[(size_t)MAXQ * CDIM];
__device__ int           g_qcnt;

// --------------------------- asm helpers -------------------------------------
__device__ __forceinline__ uint32_t sptr(const void* p) {
    return (uint32_t)__cvta_generic_to_shared(p);
}
__device__ __forceinline__ void cp16(uint32_t dst, const void* src) {
    asm volatile("cp.async.cg.shared.global [%0], [%1], 16;" :: "r"(dst), "l"(src));
}
__device__ __forceinline__ void ldsm_x4(uint32_t* d, uint32_t addr) {
    asm volatile("ldmatrix.sync.aligned.m8n8.x4.shared.b16 {%0,%1,%2,%3}, [%4];"
                 : "=r"(d[0]), "=r"(d[1]), "=r"(d[2]), "=r"(d[3]) : "r"(addr));
}
__device__ __forceinline__ void mma16816(float* c, const uint32_t* a, const uint32_t* b) {
    asm volatile(
        "mma.sync.aligned.m16n8k16.row.col.f32.bf16.bf16.f32 "
        "{%0,%1,%2,%3}, {%4,%5,%6,%7}, {%8,%9}, {%0,%1,%2,%3};"
        : "+f"(c[0]), "+f"(c[1]), "+f"(c[2]), "+f"(c[3])
        : "r"(a[0]), "r"(a[1]), "r"(a[2]), "r"(a[3]), "r"(b[0]), "r"(b[1]));
}

// --------------------------- 1) codebook prep (+queue reset) -----------------
__global__ void k_prep_e(const float* __restrict__ e) {
    int k = blockIdx.x, c = threadIdx.x;
    if (k == 0 && c == 0) g_qcnt = 0;
    float v = e[k * CDIM + c];
    g_eb[k * CDIM + c] = __float2bfloat16(v);
    float ss = v * v;
    #pragma unroll
    for (int off = 16; off > 0; off >>= 1)
        ss += __shfl_xor_sync(0xFFFFFFFFu, ss, off);
    __shared__ float part[8];
    if ((c & 31) == 0) part[c >> 5] = ss;
    __syncthreads();
    if (c == 0) {
        float t = 0.0f;
        #pragma unroll
        for (int i = 0; i < 8; i++) t += part[i];
        g_enf[k] = t;
    }
}

// --------------------------- 2) GEMM + argmin + final filter -----------------
__global__ void __launch_bounds__(256, 2)
k_gemm_argmin(const float* __restrict__ x) {
    extern __shared__ char sm[];
    float* ensh  = (float*)(sm + OFF_EN);
    int*   scnt  = (int*)(sm + OFF_CNT);
    float* rminsh= (float*)(sm + OFF_RMIN);
    int*   qslot = (int*)(sm + OFF_QSLOT);
    __nv_bfloat16* zsh = (__nv_bfloat16*)(sm + OFF_Z);

    const int tid = threadIdx.x;
    const int n0  = blockIdx.x * BM;
    const int bb  = n0 >> 10;
    const int hw0 = n0 & 1023;

    if (tid < BM) scnt[tid] = 0;
    for (int i = tid; i < KCODE; i += 256) ensh[i] = g_enf[i];

    const uint32_t zbase = sptr(sm + OFF_Z);
    const uint32_t ebase = sptr(sm + OFF_E);

    // ---- B chunk loader: single buffer, one commit group per chunk ----
    auto loadB = [&](int ck) {
        const char* src = (const char*)g_eb + (size_t)ck * BN * 512;
        #pragma unroll
        for (int i = 0; i < 8; i++) {
            int t = tid + i * 256;
            int r = t >> 5, s = t & 31;
            cp16(ebase + r * ZSB + s * 16, src + (size_t)r * 512 + s * 16);
        }
        asm volatile("cp.async.commit_group;");
    };
    loadB(0);   // prefetch chunk 0 behind the z-tile transpose

    // ---- z tile: coalesced loads, paired bf16x2 stores ----
    const float* xb = x + (size_t)bb * CDIM * HW + hw0;
    #pragma unroll 4
    for (int it = 0; it < 64; it++) {
        int p = tid + it * 256;
        int cp = p >> 7, i = p & 127;
        float v0 = xb[(size_t)(2 * cp) * HW + i];
        float v1 = xb[(size_t)(2 * cp + 1) * HW + i];
        *(__nv_bfloat162*)&zsh[i * ZS + 2 * cp] = __floats2bfloat162_rn(v0, v1);
    }

    const int lane = tid & 31, wid = tid >> 5;
    const int qr = lane >> 2, qc = lane & 3;
    const int rowbase = wid * 16;

    const uint32_t aoff = (uint32_t)(rowbase + (lane & 7) + ((lane >> 3) & 1) * 8) * ZSB
                        + ((lane >> 4) & 1) * 16;
    const uint32_t boff = (uint32_t)((lane & 7) + ((lane >> 4) & 1) * 8) * ZSB
                        + ((lane >> 3) & 1) * 16;

    float rmin0 = 3.0e38f, rmin1 = 3.0e38f;
    const int row0 = rowbase + qr, row1 = rowbase + 8 + qr;

    for (int ck = 0; ck < NCHUNK; ck++) {
        asm volatile("cp.async.wait_group 0;");
        __syncthreads();                 // B(ck) visible (z tile too at ck=0)

        float acc[8][4];
        #pragma unroll
        for (int nt = 0; nt < 8; nt++)
            #pragma unroll
            for (int i = 0; i < 4; i++) acc[nt][i] = 0.0f;

        #pragma unroll
        for (int kk = 0; kk < 16; kk++) {
            uint32_t afr[4];
            ldsm_x4(afr, zbase + aoff + kk * 32);
            uint32_t bfr[4][4];
            #pragma unroll
            for (int p = 0; p < 4; p++)
                ldsm_x4(bfr[p], ebase + boff + p * (16 * ZSB) + kk * 32);
            #pragma unroll
            for (int p = 0; p < 4; p++) {
                mma16816(acc[2 * p + 0], afr, &bfr[p][0]);
                mma16816(acc[2 * p + 1], afr, &bfr[p][2]);
            }
        }
        __syncthreads();                 // all warps done reading B(ck)
        if (ck + 1 < NCHUNK) loadB(ck + 1);   // overlaps with epilogue below

        // ---- pass 1: scores in place + exact running min ----
        float m0 = 3.0e38f, m1 = 3.0e38f;
        #pragma unroll
        for (int nt = 0; nt < 8; nt++) {
            float en0 = ensh[ck * BN + nt * 8 + 2 * qc + 0];
            float en1 = ensh[ck * BN + nt * 8 + 2 * qc + 1];
            acc[nt][0] = en0 - 2.0f * acc[nt][0];
            acc[nt][1] = en1 - 2.0f * acc[nt][1];
            acc[nt][2] = en0 - 2.0f * acc[nt][2];
            acc[nt][3] = en1 - 2.0f * acc[nt][3];
            m0 = fminf(m0, fminf(acc[nt][0], acc[nt][1]));
            m1 = fminf(m1, fminf(acc[nt][2], acc[nt][3]));
        }
        m0 = fminf(m0, __shfl_xor_sync(0xFFFFFFFFu, m0, 1));
        m0 = fminf(m0, __shfl_xor_sync(0xFFFFFFFFu, m0, 2));
        m1 = fminf(m1, __shfl_xor_sync(0xFFFFFFFFu, m1, 1));
        m1 = fminf(m1, __shfl_xor_sync(0xFFFFFFFFu, m1, 2));
        rmin0 = fminf(rmin0, m0);
        rmin1 = fminf(rmin1, m1);
        const float thr0 = rmin0 + MARGIN, thr1 = rmin1 + MARGIN;

        // ---- pass 2: rare pushes of (score, idx) to global slots ----
        #pragma unroll
        for (int nt = 0; nt < 8; nt++) {
            int kg = ck * BN + nt * 8 + 2 * qc;
            if (acc[nt][0] <= thr0) {
                int p = atomicAdd(&scnt[row0], 1);
                if (p < CAP) { g_csv[(size_t)(n0 + row0) * CAP + p] = acc[nt][0];
                               g_civ[(size_t)(n0 + row0) * CAP + p] = kg; }
            }
            if (acc[nt][1] <= thr0) {
                int p = atomicAdd(&scnt[row0], 1);
                if (p < CAP) { g_csv[(size_t)(n0 + row0) * CAP + p] = acc[nt][1];
                               g_civ[(size_t)(n0 + row0) * CAP + p] = kg + 1; }
            }
            if (acc[nt][2] <= thr1) {
                int p = atomicAdd(&scnt[row1], 1);
                if (p < CAP) { g_csv[(size_t)(n0 + row1) * CAP + p] = acc[nt][2];
                               g_civ[(size_t)(n0 + row1) * CAP + p] = kg; }
            }
            if (acc[nt][3] <= thr1) {
                int p = atomicAdd(&scnt[row1], 1);
                if (p < CAP) { g_csv[(size_t)(n0 + row1) * CAP + p] = acc[nt][3];
                               g_civ[(size_t)(n0 + row1) * CAP + p] = kg + 1; }
            }
        }
    }

    // ---- publish per-row final mins ----
    if (qc == 0) { rminsh[row0] = rmin0; rminsh[row1] = rmin1; }
    __syncthreads();

    // ---- final filter + classify (128 threads, one row each) ----
    if (tid < BM) {
        int t = tid, n = n0 + t;
        int cnt = scnt[t];
        if (cnt > CAP) {                         // overflow: full-scan fallback
            int q = atomicAdd(&g_qcnt, 1);
            qslot[t] = q; g_qn[q] = n; g_qc[q] = KCODE;
        } else {
            float thr = rminsh[t] + FMARGIN;
            int surv = 0, uniq = 0;
            for (int i = 0; i < cnt; i++)
                if (g_csv[(size_t)n * CAP + i] <= thr) { surv++; uniq = g_civ[(size_t)n * CAP + i]; }
            if (surv == 1) {
                g_best[n] = uniq; qslot[t] = -1;
            } else {
                int q = atomicAdd(&g_qcnt, 1);
                qslot[t] = q; g_qn[q] = n; g_qc[q] = surv;
                int w = 0;
                for (int i = 0; i < cnt; i++)
                    if (g_csv[(size_t)n * CAP + i] <= thr)
                        g_qcd[(size_t)q * CAP + (w++)] = g_civ[(size_t)n * CAP + i];
            }
        }
    }
    __syncthreads();

    // ---- coalesced fp32 z export for queued rows ----
    {
        const int ei = tid & 127;          // hw row (consecutive within warp)
        const int ch = tid >> 7;           // channel phase
        int q = qslot[ei];
        if (q >= 0 && q < MAXQ) {
            #pragma unroll 4
            for (int cc = 0; cc < 128; cc++) {
                int c = cc * 2 + ch;
                g_zq[(size_t)q * CDIM + c] = xb[(size_t)c * HW + ei];
            }
        }
    }
}

// --------------------------- 3) fp64 exact rescore ---------------------------
__global__ void k_rescore(const float* __restrict__ x, const float* __restrict__ e) {
    const int lane = threadIdx.x & 31;
    const int wglob = (blockIdx.x * blockDim.x + threadIdx.x) >> 5;
    const int nwarps = (gridDim.x * blockDim.x) >> 5;
    const int q = g_qcnt;

    for (int it = wglob; it < q; it += nwarps) {
        int n = g_qn[it];
        float z[8];
        if (it < MAXQ) {
            #pragma unroll
            for (int j = 0; j < 8; j++) z[j] = g_zq[(size_t)it * CDIM + lane + 32 * j];
        } else {   // export overflow: strided read from x
            int bb = n >> 10, hw = n & 1023;
            const float* xp = x + (size_t)bb * CDIM * HW + hw;
            #pragma unroll
            for (int j = 0; j < 8; j++) z[j] = xp[(size_t)(lane + 32 * j) * HW];
        }

        int cnt = g_qc[it];
        double bestS = 1e300;
        int bestK = 0x7FFFFFFF;
        const bool full = (cnt >= KCODE);
        const int iters = full ? KCODE : cnt;
        for (int i = 0; i < iters; i++) {
            int k = full ? i : g_qcd[(size_t)it * CAP + i];
            const float* er = e + (size_t)k * CDIM;
            double d = 0.0, en = 0.0;
            #pragma unroll
            for (int j = 0; j < 8; j++) {
                double ev = (double)er[lane + 32 * j];
                d  += (double)z[j] * ev;
                en += ev * ev;
            }
            #pragma unroll
            for (int off = 16; off > 0; off >>= 1) {
                d  += __shfl_xor_sync(0xFFFFFFFFu, d, off);
                en += __shfl_xor_sync(0xFFFFFFFFu, en, off);
            }
            double s = en - 2.0 * d;
            if (s < bestS || (s == bestS && k < bestK)) { bestS = s; bestK = k; }
        }
        if (lane == 0) g_best[n] = bestK;
    }
}

// --------------------------- 4) gather (512 threads, 32 rows, full occ) ------
__global__ void __launch_bounds__(512)
k_gather(const float* __restrict__ e, float* __restrict__ out) {
    __shared__ float rows[32][257];
    __shared__ int sidx[32];
    const int tid = threadIdx.x, lane = tid & 31, wid = tid >> 5;   // wid 0..15
    const int n0 = blockIdx.x * 32;
    const int bb = n0 >> 10, hw0 = n0 & 1023;

    if (tid < 32) sidx[tid] = g_best[n0 + tid];
    __syncthreads();

    // fill: 16 warps, 2 rows each
    for (int v = wid; v < 32; v += 16) {
        const float* er = e + (size_t)sidx[v] * CDIM;
        #pragma unroll
        for (int j = 0; j < 8; j++)
            rows[v][lane + 32 * j] = er[lane + 32 * j];
    }
    __syncthreads();

    // store: 16 warps sweep 256 channels, 128B-coalesced per instr
    for (int c = wid; c < CDIM; c += 16)
        out[((size_t)bb * CDIM + c) * HW + hw0 + lane] = rows[lane][c];
}

// --------------------------- launch ------------------------------------------
extern "C" void kernel_launch(void* const* d_in, const int* in_sizes, int n_in,
                              void* d_out, int out_size) {
    const float* x = (const float*)d_in[0];
    const float* e = (const float*)d_in[1];
    if (n_in >= 2 && in_sizes[0] == KCODE * CDIM) {  // robust to input order
        x = (const float*)d_in[1];
        e = (const float*)d_in[0];
    }
    float* out = (float*)d_out;

    cudaFuncSetAttribute(k_gemm_argmin, cudaFuncAttributeMaxDynamicSharedMemorySize,
                         SMEM_TOTAL);

    k_prep_e<<<KCODE, CDIM>>>(e);
    k_gemm_argmin<<<NVEC / BM, 256, SMEM_TOTAL>>>(x);
    k_rescore<<<296, 256>>>(x, e);
    k_gather<<<NVEC / 32, 512>>>(e, out);
}